// round 8
// baseline (speedup 1.0000x reference)
#include <cuda_runtime.h>
#include <math.h>

#define E 100
#define V 3
#define B_TOT 8192
#define S 100
#define T 10
#define NB 32                 // batches per M3 CTA (8192 = 256*32 exactly)
#define YPAD 304              // g_y row stride in floats (f4-aligned)

static constexpr float SCALE = 0.1f;            // 1/sqrt(100)
static constexpr float PADV  = -4294967295.0f;  // -(2^32)+1

// Device scratch (static allocation — allowed)
__device__ __align__(16) float g_of2[V * E];
__device__ __align__(16) float g_of3[V * E];
__device__ __align__(16) float g_C1[V * E];    // [v*E+e]
__device__ __align__(16) float g_C2[V * E];    // [v*E+e]
__device__ float g_d1[V];
__device__ float g_d2[V];
__device__ __align__(16) float g_y[(size_t)B_TOT * YPAD];   // y[b][v*100+e], padded

__device__ __forceinline__ float dot4(float4 a, float4 b) {
    return a.x * b.x + a.y * b.y + a.z * b.z + a.w * b.w;
}

// ---------------------------------------------------------------------------
// P1: of2 = vk@fc2_w.T + fc2_b ; of3 = vk@fc3_w.T + fc3_b   (1 block)
// ---------------------------------------------------------------------------
__global__ void __launch_bounds__(256)
mvke_p1(const float* __restrict__ vk,
        const float* __restrict__ fc2_w, const float* __restrict__ fc2_b,
        const float* __restrict__ fc3_w, const float* __restrict__ fc3_b)
{
    __shared__ float vks[V * E];
    const int tid = threadIdx.x;
    for (int i = tid; i < V * E; i += 256) vks[i] = vk[i];
    __syncthreads();

    if (tid < E) {
        const int j = tid;
        const float4* wr = (const float4*)(fc2_w + j * E);
        float a0 = 0.f, a1 = 0.f, a2 = 0.f;
        #pragma unroll
        for (int i4 = 0; i4 < 25; i4++) {
            float4 w = __ldg(wr + i4);
            const float* v0 = vks + 0 * E + 4 * i4;
            const float* v1 = vks + 1 * E + 4 * i4;
            const float* v2 = vks + 2 * E + 4 * i4;
            a0 += w.x * v0[0] + w.y * v0[1] + w.z * v0[2] + w.w * v0[3];
            a1 += w.x * v1[0] + w.y * v1[1] + w.z * v1[2] + w.w * v1[3];
            a2 += w.x * v2[0] + w.y * v2[1] + w.z * v2[2] + w.w * v2[3];
        }
        float bb = fc2_b[j];
        g_of2[0 * E + j] = a0 + bb;
        g_of2[1 * E + j] = a1 + bb;
        g_of2[2 * E + j] = a2 + bb;
    } else if (tid >= 128 && tid < 128 + E) {
        const int j = tid - 128;
        const float4* wr = (const float4*)(fc3_w + j * E);
        float a0 = 0.f, a1 = 0.f, a2 = 0.f;
        #pragma unroll
        for (int i4 = 0; i4 < 25; i4++) {
            float4 w = __ldg(wr + i4);
            const float* v0 = vks + 0 * E + 4 * i4;
            const float* v1 = vks + 1 * E + 4 * i4;
            const float* v2 = vks + 2 * E + 4 * i4;
            a0 += w.x * v0[0] + w.y * v0[1] + w.z * v0[2] + w.w * v0[3];
            a1 += w.x * v1[0] + w.y * v1[1] + w.z * v1[2] + w.w * v1[3];
            a2 += w.x * v2[0] + w.y * v2[1] + w.z * v2[2] + w.w * v2[3];
        }
        float bb = fc3_b[j];
        g_of3[0 * E + j] = a0 + bb;
        g_of3[1 * E + j] = a1 + bb;
        g_of3[2 * E + j] = a2 + bb;
    }
}

// ---------------------------------------------------------------------------
// P2: C1/d1 (block 0, from fc1/of2), C2/d2 (block 1, from fc4/of3)
// ---------------------------------------------------------------------------
__global__ void __launch_bounds__(384)
mvke_p2(const float* __restrict__ fc1_w, const float* __restrict__ fc1_b,
        const float* __restrict__ fc4_w, const float* __restrict__ fc4_b)
{
    const bool blk0 = (blockIdx.x == 0);
    const float* w  = blk0 ? fc1_w : fc4_w;
    const float* bb = blk0 ? fc1_b : fc4_b;
    const float* of = blk0 ? g_of2 : g_of3;
    float* C = blk0 ? g_C1 : g_C2;
    float* d = blk0 ? g_d1 : g_d2;
    const int tid = threadIdx.x;

    if (tid < V * E) {
        const int v = tid / E, e = tid % E;
        float c = 0.f;
        #pragma unroll 10
        for (int j = 0; j < E; j++) c += __ldg(w + j * E + e) * __ldg(of + v * E + j);
        C[tid] = c;
    } else if (tid < V * E + V) {
        const int v = tid - V * E;
        float dd = 0.f;
        #pragma unroll 10
        for (int j = 0; j < E; j++) dd += __ldg(bb + j) * __ldg(of + v * E + j);
        d[v] = dd;
    }
}

// ---------------------------------------------------------------------------
// M1: per-batch CTA, phases A-D, writes y[b] to g_y.
// ---------------------------------------------------------------------------
#define M1_C1  0       // 300
#define M1_M1  300     // 400  [s][v0,v1,v2,pad]
#define M1_SM1 700     // 400
#define M1_YP  1100    // 1200 [w*300 + v*100 + e]
#define M1_YS  2300    // 300
#define M1_TOT 2600

__global__ void __launch_bounds__(128, 8)
mvke_m1(const float* __restrict__ x)
{
    __shared__ __align__(16) float sm[M1_TOT];
    __shared__ float d1s[V];
    float* C1s  = sm + M1_C1;
    float* m1s  = sm + M1_M1;
    float* sm1s = sm + M1_SM1;
    float* yp   = sm + M1_YP;
    float* ys   = sm + M1_YS;

    const int b    = blockIdx.x;
    const int tid  = threadIdx.x;
    const int wid  = tid >> 5;
    const int lane = tid & 31;
    const int grp  = lane >> 3;
    const int idx  = lane & 7;

    const float4* xb4 = (const float4*)(x + (size_t)b * S * E);

    // ---- Phase A: stage C1, d1 ----
    if (tid < 75) ((float4*)C1s)[tid] = ((const float4*)g_C1)[tid];
    if (tid >= 112 && tid < 112 + V) d1s[tid - 112] = g_d1[tid - 112];
    __syncthreads();

    const float4* C1v0 = (const float4*)(C1s + 0 * E);
    const float4* C1v1 = (const float4*)(C1s + 1 * E);
    const float4* C1v2 = (const float4*)(C1s + 2 * E);

    // ---- Phase B: m1[s][v] ----
    {
        float4 c1r0[3], c1r1[3], c1r2[3];
        #pragma unroll
        for (int c = 0; c < 3; c++) {
            c1r0[c] = C1v0[idx + 8 * c];
            c1r1[c] = C1v1[idx + 8 * c];
            c1r2[c] = C1v2[idx + 8 * c];
        }
        #pragma unroll
        for (int sup = 0; sup < 7; sup++) {
            const int s = sup * 16 + (wid << 2) + grp;
            const bool srow = (s < S);
            float a0 = 0.f, a1 = 0.f, a2 = 0.f, asum = 0.f;
            #pragma unroll
            for (int c = 0; c < 3; c++) {
                if (srow) {
                    float4 xv = __ldg(&xb4[s * 25 + idx + 8 * c]);
                    a0 += dot4(xv, c1r0[c]);
                    a1 += dot4(xv, c1r1[c]);
                    a2 += dot4(xv, c1r2[c]);
                    asum += fabsf(xv.x) + fabsf(xv.y) + fabsf(xv.z) + fabsf(xv.w);
                }
            }
            if (idx == 0 && srow) {
                float4 xt = __ldg(&xb4[s * 25 + 24]);
                float4 t0 = C1v0[24], t1 = C1v1[24], t2 = C1v2[24];
                a0 += dot4(xt, t0);
                a1 += dot4(xt, t1);
                a2 += dot4(xt, t2);
                asum += fabsf(xt.x) + fabsf(xt.y) + fabsf(xt.z) + fabsf(xt.w);
            }
            const unsigned bal = __ballot_sync(0xffffffffu, asum != 0.f);
            const bool nonzero = ((bal >> (grp << 3)) & 0xffu) != 0u;
            #pragma unroll
            for (int off = 4; off; off >>= 1) {
                a0 += __shfl_xor_sync(0xffffffffu, a0, off);
                a1 += __shfl_xor_sync(0xffffffffu, a1, off);
                a2 += __shfl_xor_sync(0xffffffffu, a2, off);
            }
            if (idx == 0 && srow) {
                float4 mv;
                if (!nonzero) { mv.x = PADV; mv.y = PADV; mv.z = PADV; }
                else {
                    mv.x = SCALE * (a0 + d1s[0]);
                    mv.y = SCALE * (a1 + d1s[1]);
                    mv.z = SCALE * (a2 + d1s[2]);
                }
                mv.w = 0.f;
                ((float4*)m1s)[s] = mv;
            }
        }
    }
    __syncthreads();

    // ---- Phase C: softmax over s per v ----
    if (wid < V) {
        const int v = wid;
        float vals[4];
        float mx = -INFINITY;
        #pragma unroll
        for (int k = 0; k < 4; k++) {
            int s = lane + 32 * k;
            vals[k] = (s < S) ? m1s[s * 4 + v] : -INFINITY;
            mx = fmaxf(mx, vals[k]);
        }
        #pragma unroll
        for (int off = 16; off; off >>= 1) mx = fmaxf(mx, __shfl_xor_sync(0xffffffffu, mx, off));
        float sum = 0.f;
        #pragma unroll
        for (int k = 0; k < 4; k++) {
            int s = lane + 32 * k;
            vals[k] = (s < S) ? __expf(vals[k] - mx) : 0.f;
            sum += vals[k];
        }
        #pragma unroll
        for (int off = 16; off; off >>= 1) sum += __shfl_xor_sync(0xffffffffu, sum, off);
        float inv = 1.f / sum;
        #pragma unroll
        for (int k = 0; k < 4; k++) {
            int s = lane + 32 * k;
            if (s < S) sm1s[s * 4 + v] = vals[k] * inv;
        }
    }
    __syncthreads();

    // ---- Phase D: y[v,e] = sum_s sm1[s][v]*x[s,e] ----
    {
        float4 ac0 = {0.f, 0.f, 0.f, 0.f};
        float4 ac1 = {0.f, 0.f, 0.f, 0.f};
        float4 ac2 = {0.f, 0.f, 0.f, 0.f};
        #pragma unroll 5
        for (int i = 0; i < 25; i++) {
            const int s = wid + 4 * i;
            float4 w = ((const float4*)sm1s)[s];
            if (lane < 25) {
                float4 xv = __ldg(&xb4[s * 25 + lane]);
                ac0.x += w.x * xv.x; ac0.y += w.x * xv.y; ac0.z += w.x * xv.z; ac0.w += w.x * xv.w;
                ac1.x += w.y * xv.x; ac1.y += w.y * xv.y; ac1.z += w.y * xv.z; ac1.w += w.y * xv.w;
                ac2.x += w.z * xv.x; ac2.y += w.z * xv.y; ac2.z += w.z * xv.z; ac2.w += w.z * xv.w;
            }
        }
        if (lane < 25) {
            float4* yp4 = (float4*)(yp + wid * 300);
            yp4[0 * 25 + lane] = ac0;
            yp4[1 * 25 + lane] = ac1;
            yp4[2 * 25 + lane] = ac2;
        }
    }
    __syncthreads();
    #pragma unroll
    for (int i = tid; i < V * E; i += 128) {
        ys[i] = yp[i] + yp[300 + i] + yp[600 + i] + yp[900 + i];
    }
    __syncthreads();

    // ---- write y[b] ----
    if (tid < 75) {
        ((float4*)(g_y + (size_t)b * YPAD))[tid] = ((const float4*)ys)[tid];
    }
}

// ---------------------------------------------------------------------------
// M3: ws1 GEMM (W1 in smem, 32 batches/CTA) + fused epilogue (m2/sm2/g/out)
// ---------------------------------------------------------------------------
#define SM3_W1   0        // 10000 (W1 copied as-is, [ep][e])
#define SM3_B1   10000    // 100
#define SM3_Y    10100    // NB*301 = 9632  (y[b][v*100+e], b-stride 301 -> conflict-free)
#define SM3_WS   19732    // 9632  (ws1 same layout)
#define SM3_C2   29364    // 3*104 = 312 (f4-aligned rows)
#define SM3_D2   29676    // 4
#define SM3_M2   29680    // 2*32
#define SM3_G    29744    // 2*32
#define SM3_SM2  29808    // 2*32
#define SM3_TOT  29872
#define SM3_BYTES (SM3_TOT * 4)

__global__ void __launch_bounds__(256, 1)
mvke_m3(const float* __restrict__ tag,
        const float* __restrict__ fc1_w,
        const float* __restrict__ fc1_b,
        float* __restrict__ out)
{
    extern __shared__ __align__(16) float dsm[];
    float* W1s = dsm + SM3_W1;
    float* b1s = dsm + SM3_B1;
    float* ysm = dsm + SM3_Y;
    float* wss = dsm + SM3_WS;
    float* C2s = dsm + SM3_C2;
    float* d2s = dsm + SM3_D2;
    float* m2b = dsm + SM3_M2;
    float* gb  = dsm + SM3_G;
    float* s2b = dsm + SM3_SM2;

    const int tid = threadIdx.x;
    const int B0  = blockIdx.x * NB;

    // ---- stage W1, b1, C2, d2 ----
    {
        const float4* w4 = (const float4*)fc1_w;
        float4* W1s4 = (float4*)W1s;
        for (int i = tid; i < 2500; i += 256) W1s4[i] = __ldg(w4 + i);
        if (tid < E) b1s[tid] = __ldg(fc1_b + tid);
        if (tid >= 128 && tid < 128 + 75) {
            int i = tid - 128;
            ((float4*)C2s)[(i / 25) * 26 + (i % 25)] = ((const float4*)g_C2)[i];
        }
        if (tid >= 224 && tid < 224 + V) d2s[tid - 224] = g_d2[tid - 224];
    }
    // ---- stage y tile ----
    {
        const float4* gy4 = (const float4*)g_y;
        for (int i = tid; i < NB * 75; i += 256) {
            int b = i / 75, c = i % 75;
            float4 v = __ldg(&gy4[(size_t)(B0 + b) * (YPAD / 4) + c]);
            float* p = ysm + b * 301 + 4 * c;
            p[0] = v.x; p[1] = v.y; p[2] = v.z; p[3] = v.w;
        }
    }
    __syncthreads();

    // ---- GEMM: ws1[b,v,ep] = y[b,v,:].W1[ep,:] + b1[ep] ----
    {
        const int w = tid >> 5;        // warp 0..7 owns eps == w (mod 8)
        const int b = tid & 31;        // lane = batch in tile
        const float* yb = ysm + b * 301;
        #pragma unroll
        for (int kb = 0; kb < 4; kb++) {
            const int nj = (kb < 3) ? 4 : (w < 4 ? 1 : 0);
            if (nj > 0) {
                const int ep0 = w + 32 * kb;
                float acc[3][4];
                #pragma unroll
                for (int v = 0; v < 3; v++)
                    #pragma unroll
                    for (int j = 0; j < 4; j++) acc[v][j] = 0.f;
                #pragma unroll 5
                for (int e4 = 0; e4 < 25; e4++) {
                    float4 wv[4];
                    #pragma unroll
                    for (int j = 0; j < 4; j++) {
                        int ep = ep0 + 8 * j; if (ep > 99) ep = 99;   // clamped (unused lanes)
                        wv[j] = ((const float4*)(W1s + ep * E))[e4];  // broadcast LDS.128
                    }
                    #pragma unroll
                    for (int v = 0; v < 3; v++) {
                        const float* yy = yb + v * 100 + 4 * e4;
                        const float y0 = yy[0], y1 = yy[1], y2 = yy[2], y3 = yy[3];
                        #pragma unroll
                        for (int j = 0; j < 4; j++)
                            acc[v][j] += wv[j].x * y0 + wv[j].y * y1 + wv[j].z * y2 + wv[j].w * y3;
                    }
                }
                #pragma unroll
                for (int j = 0; j < 4; j++) {
                    const int ep = ep0 + 8 * j;
                    if (j < nj && ep < 100) {
                        const float bias = b1s[ep];
                        #pragma unroll
                        for (int v = 0; v < 3; v++)
                            wss[b * 301 + v * 100 + ep] = acc[v][j] + bias;  // stride 301: conflict-free
                    }
                }
            }
        }
    }
    __syncthreads();

    // ---- epilogue: 2 batches per iteration ----
    const int grpH = tid >> 7;         // 0/1
    const int t128 = tid & 127;
    const int task = t128 >> 2;        // 0..31 (30 active)
    const int q    = t128 & 3;
    const int tt   = task / 3;
    const int vv   = task - tt * 3;
    const float4* tg4 = (const float4*)tag;

    for (int p = 0; p < NB / 2; p++) {
        const int bl = 2 * p + grpH;
        const int b  = B0 + bl;
        float am = 0.f, ag = 0.f;
        if (task < 30) {
            const float* wsb = wss + bl * 301 + vv * 100;
            const float4* c2r = (const float4*)(C2s + vv * 104);
            #pragma unroll
            for (int k = 0; k < 7; k++) {
                const int f4 = q + 4 * k;
                if (f4 < 25) {
                    float4 tv = __ldg(&tg4[(size_t)b * 250 + tt * 25 + f4]);
                    am += dot4(tv, c2r[f4]);
                    const float* wp = wsb + 4 * f4;
                    ag += tv.x * wp[0] + tv.y * wp[1] + tv.z * wp[2] + tv.w * wp[3];
                }
            }
        }
        am += __shfl_xor_sync(0xffffffffu, am, 1);
        am += __shfl_xor_sync(0xffffffffu, am, 2);
        ag += __shfl_xor_sync(0xffffffffu, ag, 1);
        ag += __shfl_xor_sync(0xffffffffu, ag, 2);
        if (q == 0 && task < 30) {
            m2b[grpH * 32 + task] = SCALE * (am + d2s[vv]);
            gb [grpH * 32 + task] = ag;
        }
        __syncthreads();
        if (t128 < V) {
            const int v = t128;
            float mx = -INFINITY;
            #pragma unroll
            for (int t = 0; t < T; t++) mx = fmaxf(mx, m2b[grpH * 32 + t * 3 + v]);
            float ev[T];
            float sum = 0.f;
            #pragma unroll
            for (int t = 0; t < T; t++) {
                ev[t] = __expf(m2b[grpH * 32 + t * 3 + v] - mx);
                sum += ev[t];
            }
            float inv = 1.f / sum;
            #pragma unroll
            for (int t = 0; t < T; t++) s2b[grpH * 32 + t * 3 + v] = ev[t] * inv;
        }
        __syncthreads();
        if (t128 < T) {
            float o = 0.f;
            #pragma unroll
            for (int v = 0; v < V; v++)
                o += s2b[grpH * 32 + t128 * 3 + v] * gb[grpH * 32 + t128 * 3 + v];
            out[(size_t)b * T + t128] = o;
        }
        __syncthreads();
    }
}

// ---------------------------------------------------------------------------
extern "C" void kernel_launch(void* const* d_in, const int* in_sizes, int n_in,
                              void* d_out, int out_size) {
    const float* x     = (const float*)d_in[0];
    const float* tag   = (const float*)d_in[1];
    const float* vk    = (const float*)d_in[2];
    const float* fc1_w = (const float*)d_in[3];
    const float* fc1_b = (const float*)d_in[4];
    const float* fc2_w = (const float*)d_in[5];
    const float* fc2_b = (const float*)d_in[6];
    const float* fc3_w = (const float*)d_in[7];
    const float* fc3_b = (const float*)d_in[8];
    const float* fc4_w = (const float*)d_in[9];
    const float* fc4_b = (const float*)d_in[10];
    float* out = (float*)d_out;

    cudaFuncSetAttribute(mvke_m3, cudaFuncAttributeMaxDynamicSharedMemorySize, SM3_BYTES);

    mvke_p1<<<1, 256>>>(vk, fc2_w, fc2_b, fc3_w, fc3_b);
    mvke_p2<<<2, 384>>>(fc1_w, fc1_b, fc4_w, fc4_b);
    mvke_m1<<<B_TOT, 128>>>(x);
    mvke_m3<<<B_TOT / NB, 256, SM3_BYTES>>>(tag, fc1_w, fc1_b, out);
}

// round 9
// speedup vs baseline: 1.1200x; 1.1200x over previous
#include <cuda_runtime.h>
#include <math.h>

#define E 100
#define V 3
#define B_TOT 8192
#define S 100
#define T 10
#define NB 16                 // batches per M3 CTA (8192 = 512*16)
#define YPAD 304              // g_y row stride in floats (f4-aligned)

static constexpr float SCALE = 0.1f;            // 1/sqrt(100)
static constexpr float PADV  = -4294967295.0f;  // -(2^32)+1

// Device scratch (static allocation — allowed)
__device__ __align__(16) float g_of2[V * E];
__device__ __align__(16) float g_of3[V * E];
__device__ __align__(16) float g_C1[V * E];    // [v*E+e]
__device__ __align__(16) float g_C2[V * E];    // [v*E+e]
__device__ float g_d1[V];
__device__ float g_d2[V];
__device__ __align__(16) float g_y[(size_t)B_TOT * YPAD];   // y[b][v*100+e], padded

__device__ __forceinline__ float dot4(float4 a, float4 b) {
    return a.x * b.x + a.y * b.y + a.z * b.z + a.w * b.w;
}

// ---------------------------------------------------------------------------
// P1: of2 = vk@fc2_w.T + fc2_b ; of3 = vk@fc3_w.T + fc3_b   (1 block)
// ---------------------------------------------------------------------------
__global__ void __launch_bounds__(256)
mvke_p1(const float* __restrict__ vk,
        const float* __restrict__ fc2_w, const float* __restrict__ fc2_b,
        const float* __restrict__ fc3_w, const float* __restrict__ fc3_b)
{
    __shared__ float vks[V * E];
    const int tid = threadIdx.x;
    for (int i = tid; i < V * E; i += 256) vks[i] = vk[i];
    __syncthreads();

    if (tid < E) {
        const int j = tid;
        const float4* wr = (const float4*)(fc2_w + j * E);
        float a0 = 0.f, a1 = 0.f, a2 = 0.f;
        #pragma unroll
        for (int i4 = 0; i4 < 25; i4++) {
            float4 w = __ldg(wr + i4);
            const float* v0 = vks + 0 * E + 4 * i4;
            const float* v1 = vks + 1 * E + 4 * i4;
            const float* v2 = vks + 2 * E + 4 * i4;
            a0 += w.x * v0[0] + w.y * v0[1] + w.z * v0[2] + w.w * v0[3];
            a1 += w.x * v1[0] + w.y * v1[1] + w.z * v1[2] + w.w * v1[3];
            a2 += w.x * v2[0] + w.y * v2[1] + w.z * v2[2] + w.w * v2[3];
        }
        float bb = fc2_b[j];
        g_of2[0 * E + j] = a0 + bb;
        g_of2[1 * E + j] = a1 + bb;
        g_of2[2 * E + j] = a2 + bb;
    } else if (tid >= 128 && tid < 128 + E) {
        const int j = tid - 128;
        const float4* wr = (const float4*)(fc3_w + j * E);
        float a0 = 0.f, a1 = 0.f, a2 = 0.f;
        #pragma unroll
        for (int i4 = 0; i4 < 25; i4++) {
            float4 w = __ldg(wr + i4);
            const float* v0 = vks + 0 * E + 4 * i4;
            const float* v1 = vks + 1 * E + 4 * i4;
            const float* v2 = vks + 2 * E + 4 * i4;
            a0 += w.x * v0[0] + w.y * v0[1] + w.z * v0[2] + w.w * v0[3];
            a1 += w.x * v1[0] + w.y * v1[1] + w.z * v1[2] + w.w * v1[3];
            a2 += w.x * v2[0] + w.y * v2[1] + w.z * v2[2] + w.w * v2[3];
        }
        float bb = fc3_b[j];
        g_of3[0 * E + j] = a0 + bb;
        g_of3[1 * E + j] = a1 + bb;
        g_of3[2 * E + j] = a2 + bb;
    }
}

// ---------------------------------------------------------------------------
// P2: C1/d1 (block 0), C2/d2 (block 1)
// ---------------------------------------------------------------------------
__global__ void __launch_bounds__(384)
mvke_p2(const float* __restrict__ fc1_w, const float* __restrict__ fc1_b,
        const float* __restrict__ fc4_w, const float* __restrict__ fc4_b)
{
    const bool blk0 = (blockIdx.x == 0);
    const float* w  = blk0 ? fc1_w : fc4_w;
    const float* bb = blk0 ? fc1_b : fc4_b;
    const float* of = blk0 ? g_of2 : g_of3;
    float* C = blk0 ? g_C1 : g_C2;
    float* d = blk0 ? g_d1 : g_d2;
    const int tid = threadIdx.x;

    if (tid < V * E) {
        const int v = tid / E, e = tid % E;
        float c = 0.f;
        #pragma unroll 10
        for (int j = 0; j < E; j++) c += __ldg(w + j * E + e) * __ldg(of + v * E + j);
        C[tid] = c;
    } else if (tid < V * E + V) {
        const int v = tid - V * E;
        float dd = 0.f;
        #pragma unroll 10
        for (int j = 0; j < E; j++) dd += __ldg(bb + j) * __ldg(of + v * E + j);
        d[v] = dd;
    }
}

// ---------------------------------------------------------------------------
// M1: per-batch CTA, phases A-D, writes y[b] to g_y.  (unchanged, proven)
// ---------------------------------------------------------------------------
#define M1_C1  0       // 300
#define M1_M1  300     // 400  [s][v0,v1,v2,pad]
#define M1_SM1 700     // 400
#define M1_YP  1100    // 1200
#define M1_YS  2300    // 300
#define M1_TOT 2600

__global__ void __launch_bounds__(128, 8)
mvke_m1(const float* __restrict__ x)
{
    __shared__ __align__(16) float sm[M1_TOT];
    __shared__ float d1s[V];
    float* C1s  = sm + M1_C1;
    float* m1s  = sm + M1_M1;
    float* sm1s = sm + M1_SM1;
    float* yp   = sm + M1_YP;
    float* ys   = sm + M1_YS;

    const int b    = blockIdx.x;
    const int tid  = threadIdx.x;
    const int wid  = tid >> 5;
    const int lane = tid & 31;
    const int grp  = lane >> 3;
    const int idx  = lane & 7;

    const float4* xb4 = (const float4*)(x + (size_t)b * S * E);

    if (tid < 75) ((float4*)C1s)[tid] = ((const float4*)g_C1)[tid];
    if (tid >= 112 && tid < 112 + V) d1s[tid - 112] = g_d1[tid - 112];
    __syncthreads();

    const float4* C1v0 = (const float4*)(C1s + 0 * E);
    const float4* C1v1 = (const float4*)(C1s + 1 * E);
    const float4* C1v2 = (const float4*)(C1s + 2 * E);

    // Phase B
    {
        float4 c1r0[3], c1r1[3], c1r2[3];
        #pragma unroll
        for (int c = 0; c < 3; c++) {
            c1r0[c] = C1v0[idx + 8 * c];
            c1r1[c] = C1v1[idx + 8 * c];
            c1r2[c] = C1v2[idx + 8 * c];
        }
        #pragma unroll
        for (int sup = 0; sup < 7; sup++) {
            const int s = sup * 16 + (wid << 2) + grp;
            const bool srow = (s < S);
            float a0 = 0.f, a1 = 0.f, a2 = 0.f, asum = 0.f;
            #pragma unroll
            for (int c = 0; c < 3; c++) {
                if (srow) {
                    float4 xv = __ldg(&xb4[s * 25 + idx + 8 * c]);
                    a0 += dot4(xv, c1r0[c]);
                    a1 += dot4(xv, c1r1[c]);
                    a2 += dot4(xv, c1r2[c]);
                    asum += fabsf(xv.x) + fabsf(xv.y) + fabsf(xv.z) + fabsf(xv.w);
                }
            }
            if (idx == 0 && srow) {
                float4 xt = __ldg(&xb4[s * 25 + 24]);
                float4 t0 = C1v0[24], t1 = C1v1[24], t2 = C1v2[24];
                a0 += dot4(xt, t0);
                a1 += dot4(xt, t1);
                a2 += dot4(xt, t2);
                asum += fabsf(xt.x) + fabsf(xt.y) + fabsf(xt.z) + fabsf(xt.w);
            }
            const unsigned bal = __ballot_sync(0xffffffffu, asum != 0.f);
            const bool nonzero = ((bal >> (grp << 3)) & 0xffu) != 0u;
            #pragma unroll
            for (int off = 4; off; off >>= 1) {
                a0 += __shfl_xor_sync(0xffffffffu, a0, off);
                a1 += __shfl_xor_sync(0xffffffffu, a1, off);
                a2 += __shfl_xor_sync(0xffffffffu, a2, off);
            }
            if (idx == 0 && srow) {
                float4 mv;
                if (!nonzero) { mv.x = PADV; mv.y = PADV; mv.z = PADV; }
                else {
                    mv.x = SCALE * (a0 + d1s[0]);
                    mv.y = SCALE * (a1 + d1s[1]);
                    mv.z = SCALE * (a2 + d1s[2]);
                }
                mv.w = 0.f;
                ((float4*)m1s)[s] = mv;
            }
        }
    }
    __syncthreads();

    // Phase C: softmax over s per v
    if (wid < V) {
        const int v = wid;
        float vals[4];
        float mx = -INFINITY;
        #pragma unroll
        for (int k = 0; k < 4; k++) {
            int s = lane + 32 * k;
            vals[k] = (s < S) ? m1s[s * 4 + v] : -INFINITY;
            mx = fmaxf(mx, vals[k]);
        }
        #pragma unroll
        for (int off = 16; off; off >>= 1) mx = fmaxf(mx, __shfl_xor_sync(0xffffffffu, mx, off));
        float sum = 0.f;
        #pragma unroll
        for (int k = 0; k < 4; k++) {
            int s = lane + 32 * k;
            vals[k] = (s < S) ? __expf(vals[k] - mx) : 0.f;
            sum += vals[k];
        }
        #pragma unroll
        for (int off = 16; off; off >>= 1) sum += __shfl_xor_sync(0xffffffffu, sum, off);
        float inv = 1.f / sum;
        #pragma unroll
        for (int k = 0; k < 4; k++) {
            int s = lane + 32 * k;
            if (s < S) sm1s[s * 4 + v] = vals[k] * inv;
        }
    }
    __syncthreads();

    // Phase D
    {
        float4 ac0 = {0.f, 0.f, 0.f, 0.f};
        float4 ac1 = {0.f, 0.f, 0.f, 0.f};
        float4 ac2 = {0.f, 0.f, 0.f, 0.f};
        #pragma unroll 5
        for (int i = 0; i < 25; i++) {
            const int s = wid + 4 * i;
            float4 w = ((const float4*)sm1s)[s];
            if (lane < 25) {
                float4 xv = __ldg(&xb4[s * 25 + lane]);
                ac0.x += w.x * xv.x; ac0.y += w.x * xv.y; ac0.z += w.x * xv.z; ac0.w += w.x * xv.w;
                ac1.x += w.y * xv.x; ac1.y += w.y * xv.y; ac1.z += w.y * xv.z; ac1.w += w.y * xv.w;
                ac2.x += w.z * xv.x; ac2.y += w.z * xv.y; ac2.z += w.z * xv.z; ac2.w += w.z * xv.w;
            }
        }
        if (lane < 25) {
            float4* yp4 = (float4*)(yp + wid * 300);
            yp4[0 * 25 + lane] = ac0;
            yp4[1 * 25 + lane] = ac1;
            yp4[2 * 25 + lane] = ac2;
        }
    }
    __syncthreads();
    #pragma unroll
    for (int i = tid; i < V * E; i += 128) {
        ys[i] = yp[i] + yp[300 + i] + yp[600 + i] + yp[900 + i];
    }
    __syncthreads();

    if (tid < 75) {
        ((float4*)(g_y + (size_t)b * YPAD))[tid] = ((const float4*)ys)[tid];
    }
}

// ---------------------------------------------------------------------------
// M3: ws1 GEMM (W1 in smem, 16 batches/CTA) + parallel fused epilogue
// ---------------------------------------------------------------------------
#define SM3_W1   0        // 10000  [ep][e]
#define SM3_B1   10000    // 100
#define SM3_Y    10100    // NB*301 = 4816  (y; reused as tag buffer in epilogue)
#define SM3_WS   14916    // 4816   ws1[b*301 + v*100 + ep]
#define SM3_C2   19732    // 3*104 = 312
#define SM3_D2   20044    // 4
#define SM3_M2   20048    // 120   (4 batches * 30 tasks)
#define SM3_G    20168    // 120
#define SM3_SM2  20288    // 120
#define SM3_TOT  20408
#define SM3_BYTES (SM3_TOT * 4)     // 81632 B -> 2 CTAs/SM

__global__ void __launch_bounds__(256, 1)
mvke_m3(const float* __restrict__ tag,
        const float* __restrict__ fc1_w,
        const float* __restrict__ fc1_b,
        float* __restrict__ out)
{
    extern __shared__ __align__(16) float dsm[];
    float* W1s = dsm + SM3_W1;
    float* b1s = dsm + SM3_B1;
    float* ysm = dsm + SM3_Y;      // later: tag buffer (4 batches * 1000)
    float* wss = dsm + SM3_WS;
    float* C2s = dsm + SM3_C2;
    float* d2s = dsm + SM3_D2;
    float* m2b = dsm + SM3_M2;
    float* gb  = dsm + SM3_G;
    float* s2b = dsm + SM3_SM2;

    const int tid = threadIdx.x;
    const int B0  = blockIdx.x * NB;

    // ---- stage W1, b1, C2, d2, y tile ----
    {
        const float4* w4 = (const float4*)fc1_w;
        float4* W1s4 = (float4*)W1s;
        for (int i = tid; i < 2500; i += 256) W1s4[i] = __ldg(w4 + i);
        if (tid < E) b1s[tid] = __ldg(fc1_b + tid);
        if (tid >= 128 && tid < 128 + 75) {
            int i = tid - 128;
            ((float4*)C2s)[(i / 25) * 26 + (i % 25)] = ((const float4*)g_C2)[i];
        }
        if (tid >= 224 && tid < 224 + V) d2s[tid - 224] = g_d2[tid - 224];

        const float4* gy4 = (const float4*)g_y;
        for (int i = tid; i < NB * 75; i += 256) {
            int b = i / 75, c = i % 75;
            float4 v = __ldg(&gy4[(size_t)(B0 + b) * (YPAD / 4) + c]);
            float* p = ysm + b * 301 + 4 * c;
            p[0] = v.x; p[1] = v.y; p[2] = v.z; p[3] = v.w;
        }
    }
    __syncthreads();

    // ---- GEMM: ws1[b,v,ep] = y[b,v,:].W1[ep,:] + b1[ep]
    //      thread = (b = tid&15, epi = tid>>4); each thread eps = epi + 16*j ----
    {
        const int b   = tid & 15;
        const int epi = tid >> 4;          // 0..15
        const float* yb = ysm + b * 301;
        const int nj = (epi < 4) ? 7 : 6;  // ep = epi + 16j < 100
        float acc[3][7];
        #pragma unroll
        for (int v = 0; v < 3; v++)
            #pragma unroll
            for (int j = 0; j < 7; j++) acc[v][j] = 0.f;

        #pragma unroll 5
        for (int e4 = 0; e4 < 25; e4++) {
            float y0[3], y1[3], y2[3], y3[3];
            #pragma unroll
            for (int v = 0; v < 3; v++) {
                const float* yy = yb + v * 100 + 4 * e4;
                y0[v] = yy[0]; y1[v] = yy[1]; y2[v] = yy[2]; y3[v] = yy[3];
            }
            #pragma unroll
            for (int j = 0; j < 7; j++) {
                int ep = epi + 16 * j; if (ep > 99) ep = 99;   // clamp (unused)
                float4 wv = ((const float4*)(W1s + ep * E))[e4];
                #pragma unroll
                for (int v = 0; v < 3; v++)
                    acc[v][j] += wv.x * y0[v] + wv.y * y1[v] + wv.z * y2[v] + wv.w * y3[v];
            }
        }
        #pragma unroll
        for (int j = 0; j < 7; j++) {
            const int ep = epi + 16 * j;
            if (j < nj) {
                const float bias = b1s[ep];
                #pragma unroll
                for (int v = 0; v < 3; v++)
                    wss[b * 301 + v * 100 + ep] = acc[v][j] + bias;  // stride 301: conflict-free
            }
        }
    }
    __syncthreads();

    // ---- Epilogue: groups of 4 batches, fully parallel ----
    float* tgs = ysm;                       // reuse y region: 4 * 1000 floats
    const float4* tg4 = (const float4*)tag;

    for (int p = 0; p < NB / 4; p++) {
        const int bg = 4 * p;               // first local batch of group

        // stage tag for 4 batches (coalesced)
        for (int i = tid; i < 4 * 250; i += 256) {
            const int b = i / 250, j = i % 250;
            float4 v = __ldg(&tg4[(size_t)(B0 + bg + b) * 250 + j]);
            float* pp = tgs + b * 1000 + 4 * j;
            pp[0] = v.x; pp[1] = v.y; pp[2] = v.z; pp[3] = v.w;
        }
        __syncthreads();

        // m2/g: 120 tasks, one per thread
        if (tid < 120) {
            const int b    = tid / 30;
            const int task = tid % 30;
            const int tt   = task / 3;
            const int vv   = task % 3;
            const float* tr  = tgs + b * 1000 + tt * 100;
            const float* wsb = wss + (bg + b) * 301 + vv * 100;
            const float4* c2r = (const float4*)(C2s + vv * 104);
            float am = 0.f, ag = 0.f;
            #pragma unroll 5
            for (int f4 = 0; f4 < 25; f4++) {
                float4 tv = ((const float4*)tr)[f4];
                am += dot4(tv, c2r[f4]);
                const float* wp = wsb + 4 * f4;
                ag += tv.x * wp[0] + tv.y * wp[1] + tv.z * wp[2] + tv.w * wp[3];
            }
            m2b[tid] = SCALE * (am + d2s[vv]);
            gb[tid]  = ag;
        }
        __syncthreads();

        // softmax over t: 12 threads (b,v)
        if (tid < 12) {
            const int b = tid / 3, v = tid % 3;
            float mx = -INFINITY;
            #pragma unroll
            for (int t = 0; t < T; t++) mx = fmaxf(mx, m2b[b * 30 + t * 3 + v]);
            float ev[T];
            float sum = 0.f;
            #pragma unroll
            for (int t = 0; t < T; t++) {
                ev[t] = __expf(m2b[b * 30 + t * 3 + v] - mx);
                sum += ev[t];
            }
            float inv = 1.f / sum;
            #pragma unroll
            for (int t = 0; t < T; t++) s2b[b * 30 + t * 3 + v] = ev[t] * inv;
        }
        __syncthreads();

        // out: 40 threads (b,t)
        if (tid < 40) {
            const int b = tid / 10, t = tid % 10;
            float o = 0.f;
            #pragma unroll
            for (int v = 0; v < V; v++)
                o += s2b[b * 30 + t * 3 + v] * gb[b * 30 + t * 3 + v];
            out[(size_t)(B0 + bg + b) * T + t] = o;
        }
        __syncthreads();   // protect tgs/m2b reuse next group
    }
}

// ---------------------------------------------------------------------------
extern "C" void kernel_launch(void* const* d_in, const int* in_sizes, int n_in,
                              void* d_out, int out_size) {
    const float* x     = (const float*)d_in[0];
    const float* tag   = (const float*)d_in[1];
    const float* vk    = (const float*)d_in[2];
    const float* fc1_w = (const float*)d_in[3];
    const float* fc1_b = (const float*)d_in[4];
    const float* fc2_w = (const float*)d_in[5];
    const float* fc2_b = (const float*)d_in[6];
    const float* fc3_w = (const float*)d_in[7];
    const float* fc3_b = (const float*)d_in[8];
    const float* fc4_w = (const float*)d_in[9];
    const float* fc4_b = (const float*)d_in[10];
    float* out = (float*)d_out;

    cudaFuncSetAttribute(mvke_m3, cudaFuncAttributeMaxDynamicSharedMemorySize, SM3_BYTES);

    mvke_p1<<<1, 256>>>(vk, fc2_w, fc2_b, fc3_w, fc3_b);
    mvke_p2<<<2, 384>>>(fc1_w, fc1_b, fc4_w, fc4_b);
    mvke_m1<<<B_TOT, 128>>>(x);
    mvke_m3<<<B_TOT / NB, 256, SM3_BYTES>>>(tag, fc1_w, fc1_b, out);
}

// round 10
// speedup vs baseline: 1.1384x; 1.0164x over previous
#include <cuda_runtime.h>
#include <math.h>

#define E 100
#define V 3
#define B_TOT 8192
#define S 100
#define T 10
#define NB 8                  // batches per M3 CTA (8192 = 1024*8)
#define YPAD 304              // g_y row stride in floats (f4-aligned)

static constexpr float SCALE = 0.1f;            // 1/sqrt(100)
static constexpr float PADV  = -4294967295.0f;  // -(2^32)+1

// Device scratch (static allocation — allowed)
__device__ __align__(16) float g_of2[V * E];
__device__ __align__(16) float g_of3[V * E];
__device__ __align__(16) float g_C1[V * E];    // [v*E+e]
__device__ __align__(16) float g_C2[V * E];    // [v*E+e]
__device__ float g_d1[V];
__device__ float g_d2[V];
__device__ __align__(16) float g_y[(size_t)B_TOT * YPAD];   // y[b][v*100+e], padded

__device__ __forceinline__ float dot4(float4 a, float4 b) {
    return a.x * b.x + a.y * b.y + a.z * b.z + a.w * b.w;
}

// ---------------------------------------------------------------------------
// P1: of2 = vk@fc2_w.T + fc2_b ; of3 = vk@fc3_w.T + fc3_b   (1 block)
// ---------------------------------------------------------------------------
__global__ void __launch_bounds__(256)
mvke_p1(const float* __restrict__ vk,
        const float* __restrict__ fc2_w, const float* __restrict__ fc2_b,
        const float* __restrict__ fc3_w, const float* __restrict__ fc3_b)
{
    __shared__ float vks[V * E];
    const int tid = threadIdx.x;
    for (int i = tid; i < V * E; i += 256) vks[i] = vk[i];
    __syncthreads();

    if (tid < E) {
        const int j = tid;
        const float4* wr = (const float4*)(fc2_w + j * E);
        float a0 = 0.f, a1 = 0.f, a2 = 0.f;
        #pragma unroll
        for (int i4 = 0; i4 < 25; i4++) {
            float4 w = __ldg(wr + i4);
            const float* v0 = vks + 0 * E + 4 * i4;
            const float* v1 = vks + 1 * E + 4 * i4;
            const float* v2 = vks + 2 * E + 4 * i4;
            a0 += w.x * v0[0] + w.y * v0[1] + w.z * v0[2] + w.w * v0[3];
            a1 += w.x * v1[0] + w.y * v1[1] + w.z * v1[2] + w.w * v1[3];
            a2 += w.x * v2[0] + w.y * v2[1] + w.z * v2[2] + w.w * v2[3];
        }
        float bb = fc2_b[j];
        g_of2[0 * E + j] = a0 + bb;
        g_of2[1 * E + j] = a1 + bb;
        g_of2[2 * E + j] = a2 + bb;
    } else if (tid >= 128 && tid < 128 + E) {
        const int j = tid - 128;
        const float4* wr = (const float4*)(fc3_w + j * E);
        float a0 = 0.f, a1 = 0.f, a2 = 0.f;
        #pragma unroll
        for (int i4 = 0; i4 < 25; i4++) {
            float4 w = __ldg(wr + i4);
            const float* v0 = vks + 0 * E + 4 * i4;
            const float* v1 = vks + 1 * E + 4 * i4;
            const float* v2 = vks + 2 * E + 4 * i4;
            a0 += w.x * v0[0] + w.y * v0[1] + w.z * v0[2] + w.w * v0[3];
            a1 += w.x * v1[0] + w.y * v1[1] + w.z * v1[2] + w.w * v1[3];
            a2 += w.x * v2[0] + w.y * v2[1] + w.z * v2[2] + w.w * v2[3];
        }
        float bb = fc3_b[j];
        g_of3[0 * E + j] = a0 + bb;
        g_of3[1 * E + j] = a1 + bb;
        g_of3[2 * E + j] = a2 + bb;
    }
}

// ---------------------------------------------------------------------------
// P2: C1/d1 (block 0), C2/d2 (block 1)
// ---------------------------------------------------------------------------
__global__ void __launch_bounds__(384)
mvke_p2(const float* __restrict__ fc1_w, const float* __restrict__ fc1_b,
        const float* __restrict__ fc4_w, const float* __restrict__ fc4_b)
{
    const bool blk0 = (blockIdx.x == 0);
    const float* w  = blk0 ? fc1_w : fc4_w;
    const float* bb = blk0 ? fc1_b : fc4_b;
    const float* of = blk0 ? g_of2 : g_of3;
    float* C = blk0 ? g_C1 : g_C2;
    float* d = blk0 ? g_d1 : g_d2;
    const int tid = threadIdx.x;

    if (tid < V * E) {
        const int v = tid / E, e = tid % E;
        float c = 0.f;
        #pragma unroll 10
        for (int j = 0; j < E; j++) c += __ldg(w + j * E + e) * __ldg(of + v * E + j);
        C[tid] = c;
    } else if (tid < V * E + V) {
        const int v = tid - V * E;
        float dd = 0.f;
        #pragma unroll 10
        for (int j = 0; j < E; j++) dd += __ldg(bb + j) * __ldg(of + v * E + j);
        d[v] = dd;
    }
}

// ---------------------------------------------------------------------------
// M1: per-batch CTA, phases A-D, writes y[b] to g_y.  (unchanged, proven)
// ---------------------------------------------------------------------------
#define M1_C1  0       // 300
#define M1_M1  300     // 400  [s][v0,v1,v2,pad]
#define M1_SM1 700     // 400
#define M1_YP  1100    // 1200
#define M1_YS  2300    // 300
#define M1_TOT 2600

__global__ void __launch_bounds__(128, 8)
mvke_m1(const float* __restrict__ x)
{
    __shared__ __align__(16) float sm[M1_TOT];
    __shared__ float d1s[V];
    float* C1s  = sm + M1_C1;
    float* m1s  = sm + M1_M1;
    float* sm1s = sm + M1_SM1;
    float* yp   = sm + M1_YP;
    float* ys   = sm + M1_YS;

    const int b    = blockIdx.x;
    const int tid  = threadIdx.x;
    const int wid  = tid >> 5;
    const int lane = tid & 31;
    const int grp  = lane >> 3;
    const int idx  = lane & 7;

    const float4* xb4 = (const float4*)(x + (size_t)b * S * E);

    if (tid < 75) ((float4*)C1s)[tid] = ((const float4*)g_C1)[tid];
    if (tid >= 112 && tid < 112 + V) d1s[tid - 112] = g_d1[tid - 112];
    __syncthreads();

    const float4* C1v0 = (const float4*)(C1s + 0 * E);
    const float4* C1v1 = (const float4*)(C1s + 1 * E);
    const float4* C1v2 = (const float4*)(C1s + 2 * E);

    // Phase B
    {
        float4 c1r0[3], c1r1[3], c1r2[3];
        #pragma unroll
        for (int c = 0; c < 3; c++) {
            c1r0[c] = C1v0[idx + 8 * c];
            c1r1[c] = C1v1[idx + 8 * c];
            c1r2[c] = C1v2[idx + 8 * c];
        }
        #pragma unroll
        for (int sup = 0; sup < 7; sup++) {
            const int s = sup * 16 + (wid << 2) + grp;
            const bool srow = (s < S);
            float a0 = 0.f, a1 = 0.f, a2 = 0.f, asum = 0.f;
            #pragma unroll
            for (int c = 0; c < 3; c++) {
                if (srow) {
                    float4 xv = __ldg(&xb4[s * 25 + idx + 8 * c]);
                    a0 += dot4(xv, c1r0[c]);
                    a1 += dot4(xv, c1r1[c]);
                    a2 += dot4(xv, c1r2[c]);
                    asum += fabsf(xv.x) + fabsf(xv.y) + fabsf(xv.z) + fabsf(xv.w);
                }
            }
            if (idx == 0 && srow) {
                float4 xt = __ldg(&xb4[s * 25 + 24]);
                float4 t0 = C1v0[24], t1 = C1v1[24], t2 = C1v2[24];
                a0 += dot4(xt, t0);
                a1 += dot4(xt, t1);
                a2 += dot4(xt, t2);
                asum += fabsf(xt.x) + fabsf(xt.y) + fabsf(xt.z) + fabsf(xt.w);
            }
            const unsigned bal = __ballot_sync(0xffffffffu, asum != 0.f);
            const bool nonzero = ((bal >> (grp << 3)) & 0xffu) != 0u;
            #pragma unroll
            for (int off = 4; off; off >>= 1) {
                a0 += __shfl_xor_sync(0xffffffffu, a0, off);
                a1 += __shfl_xor_sync(0xffffffffu, a1, off);
                a2 += __shfl_xor_sync(0xffffffffu, a2, off);
            }
            if (idx == 0 && srow) {
                float4 mv;
                if (!nonzero) { mv.x = PADV; mv.y = PADV; mv.z = PADV; }
                else {
                    mv.x = SCALE * (a0 + d1s[0]);
                    mv.y = SCALE * (a1 + d1s[1]);
                    mv.z = SCALE * (a2 + d1s[2]);
                }
                mv.w = 0.f;
                ((float4*)m1s)[s] = mv;
            }
        }
    }
    __syncthreads();

    // Phase C: softmax over s per v
    if (wid < V) {
        const int v = wid;
        float vals[4];
        float mx = -INFINITY;
        #pragma unroll
        for (int k = 0; k < 4; k++) {
            int s = lane + 32 * k;
            vals[k] = (s < S) ? m1s[s * 4 + v] : -INFINITY;
            mx = fmaxf(mx, vals[k]);
        }
        #pragma unroll
        for (int off = 16; off; off >>= 1) mx = fmaxf(mx, __shfl_xor_sync(0xffffffffu, mx, off));
        float sum = 0.f;
        #pragma unroll
        for (int k = 0; k < 4; k++) {
            int s = lane + 32 * k;
            vals[k] = (s < S) ? __expf(vals[k] - mx) : 0.f;
            sum += vals[k];
        }
        #pragma unroll
        for (int off = 16; off; off >>= 1) sum += __shfl_xor_sync(0xffffffffu, sum, off);
        float inv = 1.f / sum;
        #pragma unroll
        for (int k = 0; k < 4; k++) {
            int s = lane + 32 * k;
            if (s < S) sm1s[s * 4 + v] = vals[k] * inv;
        }
    }
    __syncthreads();

    // Phase D
    {
        float4 ac0 = {0.f, 0.f, 0.f, 0.f};
        float4 ac1 = {0.f, 0.f, 0.f, 0.f};
        float4 ac2 = {0.f, 0.f, 0.f, 0.f};
        #pragma unroll 5
        for (int i = 0; i < 25; i++) {
            const int s = wid + 4 * i;
            float4 w = ((const float4*)sm1s)[s];
            if (lane < 25) {
                float4 xv = __ldg(&xb4[s * 25 + lane]);
                ac0.x += w.x * xv.x; ac0.y += w.x * xv.y; ac0.z += w.x * xv.z; ac0.w += w.x * xv.w;
                ac1.x += w.y * xv.x; ac1.y += w.y * xv.y; ac1.z += w.y * xv.z; ac1.w += w.y * xv.w;
                ac2.x += w.z * xv.x; ac2.y += w.z * xv.y; ac2.z += w.z * xv.z; ac2.w += w.z * xv.w;
            }
        }
        if (lane < 25) {
            float4* yp4 = (float4*)(yp + wid * 300);
            yp4[0 * 25 + lane] = ac0;
            yp4[1 * 25 + lane] = ac1;
            yp4[2 * 25 + lane] = ac2;
        }
    }
    __syncthreads();
    #pragma unroll
    for (int i = tid; i < V * E; i += 128) {
        ys[i] = yp[i] + yp[300 + i] + yp[600 + i] + yp[900 + i];
    }
    __syncthreads();

    if (tid < 75) {
        ((float4*)(g_y + (size_t)b * YPAD))[tid] = ((const float4*)ys)[tid];
    }
}

// ---------------------------------------------------------------------------
// M3: ws1 GEMM (W1 in smem, 8 batches/CTA, 3 CTAs/SM) + single-group epilogue
// ---------------------------------------------------------------------------
#define SM3_W1   0        // 10000  [ep][e]     (reused as tag buffer: 8*1000)
#define SM3_B1   10000    // 100
#define SM3_Y    10100    // NB*300 = 2400  (stride 300: f4-aligned, conflict-free b=0..7)
#define SM3_WS   12500    // 2400   ws1[b*300 + v*100 + ep]
#define SM3_C2   14900    // 3*104 = 312
#define SM3_D2   15212    // 4
#define SM3_M2   15216    // 240   (8 batches * 30 tasks)
#define SM3_G    15456    // 240
#define SM3_SM2  15696    // 240
#define SM3_TOT  15936
#define SM3_BYTES (SM3_TOT * 4)     // 63744 B -> 3 CTAs/SM

template<int NJ>
__device__ __forceinline__ void m3_gemm_rows(
    const float* __restrict__ W1s, const float* __restrict__ b1s,
    const float* __restrict__ yb, float* __restrict__ wsb, int epi)
{
    float acc[3][NJ];
    #pragma unroll
    for (int v = 0; v < 3; v++)
        #pragma unroll
        for (int j = 0; j < NJ; j++) acc[v][j] = 0.f;

    #pragma unroll 5
    for (int e4 = 0; e4 < 25; e4++) {
        float4 yv[3];
        #pragma unroll
        for (int v = 0; v < 3; v++)
            yv[v] = ((const float4*)(yb + v * 100))[e4];      // conflict-free LDS.128
        #pragma unroll
        for (int j = 0; j < NJ; j++) {
            const int ep = epi + 32 * j;
            float4 wv = ((const float4*)(W1s + ep * E))[e4];  // broadcast LDS.128
            #pragma unroll
            for (int v = 0; v < 3; v++) acc[v][j] += dot4(wv, yv[v]);
        }
    }
    #pragma unroll
    for (int j = 0; j < NJ; j++) {
        const int ep = epi + 32 * j;
        const float bias = b1s[ep];
        #pragma unroll
        for (int v = 0; v < 3; v++)
            wsb[v * 100 + ep] = acc[v][j] + bias;
    }
}

__global__ void __launch_bounds__(256, 3)
mvke_m3(const float* __restrict__ tag,
        const float* __restrict__ fc1_w,
        const float* __restrict__ fc1_b,
        float* __restrict__ out)
{
    extern __shared__ __align__(16) float dsm[];
    float* W1s = dsm + SM3_W1;
    float* b1s = dsm + SM3_B1;
    float* ysm = dsm + SM3_Y;
    float* wss = dsm + SM3_WS;
    float* C2s = dsm + SM3_C2;
    float* d2s = dsm + SM3_D2;
    float* m2b = dsm + SM3_M2;
    float* gb  = dsm + SM3_G;
    float* s2b = dsm + SM3_SM2;

    const int tid = threadIdx.x;
    const int B0  = blockIdx.x * NB;

    // ---- stage W1, b1, C2, d2, y tile ----
    {
        const float4* w4 = (const float4*)fc1_w;
        float4* W1s4 = (float4*)W1s;
        for (int i = tid; i < 2500; i += 256) W1s4[i] = __ldg(w4 + i);
        if (tid < E) b1s[tid] = __ldg(fc1_b + tid);
        if (tid >= 128 && tid < 128 + 75) {
            int i = tid - 128;
            ((float4*)C2s)[(i / 25) * 26 + (i % 25)] = ((const float4*)g_C2)[i];
        }
        if (tid >= 224 && tid < 224 + V) d2s[tid - 224] = g_d2[tid - 224];

        const float4* gy4 = (const float4*)g_y;
        for (int i = tid; i < NB * 75; i += 256) {
            int b = i / 75, c = i % 75;
            ((float4*)(ysm + b * 300))[c] = __ldg(&gy4[(size_t)(B0 + b) * (YPAD / 4) + c]);
        }
    }
    __syncthreads();

    // ---- GEMM: ws1[b,v,ep] = y[b,v,:].W1[ep,:] + b1[ep]
    //      thread = (b = tid&7, epi = tid>>3); eps = epi + 32*j (warp-uniform NJ) ----
    {
        const int b   = tid & 7;
        const int epi = tid >> 3;          // 0..31
        const float* yb = ysm + b * 300;
        float* wsb = wss + b * 300;
        if (epi < 4) m3_gemm_rows<4>(W1s, b1s, yb, wsb, epi);
        else         m3_gemm_rows<3>(W1s, b1s, yb, wsb, epi);
    }
    __syncthreads();

    // ---- Epilogue (single group, all 8 batches) ----
    float* tgs = dsm;                       // reuse W1 region: 8 * 1000 floats
    const float4* tg4 = (const float4*)tag;

    // stage tag (coalesced)
    for (int i = tid; i < NB * 250; i += 256) {
        const int b = i / 250, j = i % 250;
        ((float4*)(tgs + b * 1000))[j] = __ldg(&tg4[(size_t)(B0 + b) * 250 + j]);
    }
    __syncthreads();

    // m2/g: 240 tasks, one per thread
    if (tid < NB * 30) {
        const int b    = tid / 30;
        const int task = tid % 30;
        const int tt   = task / 3;
        const int vv   = task % 3;
        const float* tr  = tgs + b * 1000 + tt * 100;
        const float* wsb = wss + b * 300 + vv * 100;
        const float4* c2r = (const float4*)(C2s + vv * 104);
        float am = 0.f, ag = 0.f;
        #pragma unroll 5
        for (int f4 = 0; f4 < 25; f4++) {
            float4 tv = ((const float4*)tr)[f4];
            am += dot4(tv, c2r[f4]);
            const float* wp = wsb + 4 * f4;
            ag += tv.x * wp[0] + tv.y * wp[1] + tv.z * wp[2] + tv.w * wp[3];
        }
        m2b[tid] = SCALE * (am + d2s[vv]);
        gb[tid]  = ag;
    }
    __syncthreads();

    // softmax over t: 24 threads (b,v)
    if (tid < NB * V) {
        const int b = tid / 3, v = tid % 3;
        float mx = -INFINITY;
        #pragma unroll
        for (int t = 0; t < T; t++) mx = fmaxf(mx, m2b[b * 30 + t * 3 + v]);
        float ev[T];
        float sum = 0.f;
        #pragma unroll
        for (int t = 0; t < T; t++) {
            ev[t] = __expf(m2b[b * 30 + t * 3 + v] - mx);
            sum += ev[t];
        }
        float inv = 1.f / sum;
        #pragma unroll
        for (int t = 0; t < T; t++) s2b[b * 30 + t * 3 + v] = ev[t] * inv;
    }
    __syncthreads();

    // out: 80 threads (b,t)
    if (tid < NB * T) {
        const int b = tid / 10, t = tid % 10;
        float o = 0.f;
        #pragma unroll
        for (int v = 0; v < V; v++)
            o += s2b[b * 30 + t * 3 + v] * gb[b * 30 + t * 3 + v];
        out[(size_t)(B0 + b) * T + t] = o;
    }
}

// ---------------------------------------------------------------------------
extern "C" void kernel_launch(void* const* d_in, const int* in_sizes, int n_in,
                              void* d_out, int out_size) {
    const float* x     = (const float*)d_in[0];
    const float* tag   = (const float*)d_in[1];
    const float* vk    = (const float*)d_in[2];
    const float* fc1_w = (const float*)d_in[3];
    const float* fc1_b = (const float*)d_in[4];
    const float* fc2_w = (const float*)d_in[5];
    const float* fc2_b = (const float*)d_in[6];
    const float* fc3_w = (const float*)d_in[7];
    const float* fc3_b = (const float*)d_in[8];
    const float* fc4_w = (const float*)d_in[9];
    const float* fc4_b = (const float*)d_in[10];
    float* out = (float*)d_out;

    cudaFuncSetAttribute(mvke_m3, cudaFuncAttributeMaxDynamicSharedMemorySize, SM3_BYTES);

    mvke_p1<<<1, 256>>>(vk, fc2_w, fc2_b, fc3_w, fc3_b);
    mvke_p2<<<2, 384>>>(fc1_w, fc1_b, fc4_w, fc4_b);
    mvke_m1<<<B_TOT, 128>>>(x);
    mvke_m3<<<B_TOT / NB, 256, SM3_BYTES>>>(tag, fc1_w, fc1_b, out);
}